// round 14
// baseline (speedup 1.0000x reference)
#include <cuda_runtime.h>
#include <cuda_bf16.h>
#include <cstdint>
#include <math.h>

#define N_B   256
#define K_DIM 256
#define KC 64                    // bf16 per chunk = 128 B rows
#define STAGE_BYTES 32768
#define SM_ALLOC (3 * STAGE_BYTES + 1024)

// device scratch (allocation-free rule)
__device__ __align__(1024) __nv_bfloat16 g_xh[(size_t)N_B * 32 * K_DIM];
__device__ __align__(1024) __nv_bfloat16 g_zh[(size_t)N_B * 32 * K_DIM];
__device__ __align__(256)  float g_S[N_B * N_B];
__device__ __align__(256)  float g_St[N_B * N_B];
__device__ float g_bpart[16];
__device__ unsigned g_cnt;

// ---------------------------------------------------------------------------
__device__ __forceinline__ uint32_t smem_u32(const void* p) {
    uint32_t a;
    asm("{ .reg .u64 t; cvta.to.shared.u64 t, %1; cvt.u32.u64 %0, t; }" : "=r"(a) : "l"(p));
    return a;
}
__device__ __forceinline__ void cp16(uint32_t dst, const void* src) {
    asm volatile("cp.async.cg.shared.global [%0], [%1], 16;\n" :: "r"(dst), "l"(src));
}
__device__ __forceinline__ void ldm_x4(uint32_t r[4], uint32_t addr) {
    asm volatile("ldmatrix.sync.aligned.m8n8.x4.shared.b16 {%0,%1,%2,%3}, [%4];"
                 : "=r"(r[0]), "=r"(r[1]), "=r"(r[2]), "=r"(r[3]) : "r"(addr));
}
__device__ __forceinline__ void mma_bf16(float c[4], const uint32_t a[4], const uint32_t b0,
                                         const uint32_t b1) {
    asm volatile(
        "mma.sync.aligned.m16n8k16.row.col.f32.bf16.bf16.f32 "
        "{%0,%1,%2,%3}, {%4,%5,%6,%7}, {%8,%9}, {%0,%1,%2,%3};\n"
        : "+f"(c[0]), "+f"(c[1]), "+f"(c[2]), "+f"(c[3])
        : "r"(a[0]), "r"(a[1]), "r"(a[2]), "r"(a[3]), "r"(b0), "r"(b1));
}
__device__ __forceinline__ uint32_t swz(uint32_t off) {
    return off ^ ((off >> 3) & 0x70);
}
__device__ __forceinline__ uint2 bf4(float4 v) {
    __nv_bfloat162 p0 = __floats2bfloat162_rn(v.x, v.y);
    __nv_bfloat162 p1 = __floats2bfloat162_rn(v.z, v.w);
    uint2 o;
    o.x = *(uint32_t*)&p0;
    o.y = *(uint32_t*)&p1;
    return o;
}
__device__ __forceinline__ uint32_t lds32(uint32_t addr) {
    uint32_t w;
    asm volatile("ld.shared.b32 %0, [%1];" : "=r"(w) : "r"(addr));
    return w;
}
__device__ __forceinline__ float bflo(uint32_t w) { return __uint_as_float(w << 16); }
__device__ __forceinline__ float bfhi(uint32_t w) { return __uint_as_float(w & 0xffff0000u); }

// ---------------------------------------------------------------------------
// Phase 0: fp32 -> bf16 (rn); 8 independent float4 per thread (MLP 8)
// ---------------------------------------------------------------------------
__global__ void round_kernel(const float* __restrict__ x, const float* __restrict__ z) {
    const int qtr = (N_B * 32 * K_DIM) / 16;         // 131072 float4 per quarter-tensor
    int i = blockIdx.x * blockDim.x + threadIdx.x;   // 0..131071
    float4 vx0 = ((const float4*)x)[i];
    float4 vx1 = ((const float4*)x)[i + qtr];
    float4 vx2 = ((const float4*)x)[i + 2 * qtr];
    float4 vx3 = ((const float4*)x)[i + 3 * qtr];
    float4 vz0 = ((const float4*)z)[i];
    float4 vz1 = ((const float4*)z)[i + qtr];
    float4 vz2 = ((const float4*)z)[i + 2 * qtr];
    float4 vz3 = ((const float4*)z)[i + 3 * qtr];
    *(uint2*)(g_xh + 4 * (size_t)i)             = bf4(vx0);
    *(uint2*)(g_xh + 4 * (size_t)(i + qtr))     = bf4(vx1);
    *(uint2*)(g_xh + 4 * (size_t)(i + 2 * qtr)) = bf4(vx2);
    *(uint2*)(g_xh + 4 * (size_t)(i + 3 * qtr)) = bf4(vx3);
    *(uint2*)(g_zh + 4 * (size_t)i)             = bf4(vz0);
    *(uint2*)(g_zh + 4 * (size_t)(i + qtr))     = bf4(vz1);
    *(uint2*)(g_zh + 4 * (size_t)(i + 2 * qtr)) = bf4(vz2);
    *(uint2*)(g_zh + 4 * (size_t)(i + 3 * qtr)) = bf4(vz3);
}

// ---------------------------------------------------------------------------
// Phase 1: hybrid bf16 GEMM — tensor pipe does k 0..239 (15 mma k-steps),
// FMA pipe does k 240..255 (initializes acc). 128x128 tile, 2 CTAs/SM.
// ---------------------------------------------------------------------------
__device__ __forceinline__ void load_chunk(uint32_t stg,
                                           const __nv_bfloat16* __restrict__ zg,
                                           const __nv_bfloat16* __restrict__ xg,
                                           int c, int tid) {
    const int kc = c * KC;
    const uint32_t zs = stg;
    const uint32_t xs = stg + 16384;
#pragma unroll
    for (int q = 0; q < 4; ++q) {            // Z: 128 rows x 8 segs
        int it = tid + 256 * q;
        int row = it >> 3, s = it & 7;
        cp16(zs + swz(row * 128 + s * 16), zg + (size_t)row * K_DIM + kc + s * 8);
    }
#pragma unroll
    for (int q = 0; q < 4; ++q) {            // X: 128 rows x 8 segs
        int it = tid + 256 * q;
        int row = it >> 3, s = it & 7;
        cp16(xs + swz(row * 128 + s * 16), xg + (size_t)row * K_DIM + kc + s * 8);
    }
    asm volatile("cp.async.commit_group;\n" ::);
}

// FMA-pipe partial: acc = sum over the last 16 k's of chunk 3 (bytes 96..127).
// Per thread: rows m0+mf*16+half*8+g (z), cols n0+nf*8+2*tg+par (x).
__device__ __forceinline__ void ffma_part(uint32_t stg, int m0, int n0, int lane,
                                          float acc[4][4][4]) {
    const uint32_t zs = stg;
    const uint32_t xs = stg + 16384;
    const int g  = lane >> 2;
    const int tg = lane & 3;
#pragma unroll
    for (int kp = 0; kp < 8; ++kp) {         // 8 bf16x2 words = 16 k's
        const uint32_t kb = 96 + kp * 4;
        float zf[4][2][2];                   // [mf][half][k in pair]
#pragma unroll
        for (int mf = 0; mf < 4; ++mf)
#pragma unroll
            for (int half = 0; half < 2; ++half) {
                int row = m0 + mf * 16 + half * 8 + g;
                uint32_t w = lds32(zs + swz((uint32_t)row * 128 + kb));
                zf[mf][half][0] = bflo(w);
                zf[mf][half][1] = bfhi(w);
            }
#pragma unroll
        for (int nf = 0; nf < 4; ++nf) {
#pragma unroll
            for (int par = 0; par < 2; ++par) {
                int row = n0 + nf * 8 + 2 * tg + par;
                uint32_t w = lds32(xs + swz((uint32_t)row * 128 + kb));
                float x0 = bflo(w), x1 = bfhi(w);
#pragma unroll
                for (int mf = 0; mf < 4; ++mf)
#pragma unroll
                    for (int half = 0; half < 2; ++half) {
                        acc[mf][nf][half * 2 + par] =
                            fmaf(zf[mf][half][0], x0,
                                 fmaf(zf[mf][half][1], x1,
                                      acc[mf][nf][half * 2 + par]));
                    }
            }
        }
    }
}

__device__ __forceinline__ void compute_chunk(uint32_t stg, int m0, int n0, int lane,
                                              float acc[4][4][4], int nks) {
    const uint32_t zs = stg;
    const uint32_t xs = stg + 16384;
    const int a_row16 = lane & 15;
    const int a_half  = lane >> 4;
    const int b_grp   = lane >> 3;
    const int b_row   = lane & 7;
#pragma unroll
    for (int ks = 0; ks < 4; ++ks) {
        if (ks >= nks) break;
        const uint32_t kcol = ks * 32;
        uint32_t a[4][4];
#pragma unroll
        for (int mf = 0; mf < 4; ++mf) {     // A = z rows
            int row = m0 + mf * 16 + a_row16;
            ldm_x4(a[mf], zs + swz((uint32_t)row * 128 + kcol + a_half * 16));
        }
        uint32_t b[2][4];
#pragma unroll
        for (int pf = 0; pf < 2; ++pf) {     // B = x rows (n range 32)
            int row = n0 + pf * 16 + (b_grp >> 1) * 8 + b_row;
            ldm_x4(b[pf], xs + swz((uint32_t)row * 128 + kcol + (b_grp & 1) * 16));
        }
#pragma unroll
        for (int mf = 0; mf < 4; ++mf)
#pragma unroll
            for (int nf = 0; nf < 4; ++nf)
                mma_bf16(acc[mf][nf], a[mf], b[nf >> 1][(nf & 1) * 2],
                         b[nf >> 1][(nf & 1) * 2 + 1]);
    }
}

__global__ void __launch_bounds__(256, 2) sim_kernel() {
    extern __shared__ char sm_raw[];
    uint32_t base = (smem_u32(sm_raw) + 1023u) & ~1023u;

    const int tid  = threadIdx.x;
    const int lane = tid & 31;
    const int wid  = tid >> 5;
    const int w_m  = wid & 1;       // 2 warps over 128 z rows
    const int w_n  = wid >> 1;      // 4 warps over 128 x rows
    const int m0   = w_m * 64;
    const int n0   = w_n * 32;

    const __nv_bfloat16* zg = g_zh + (size_t)blockIdx.y * 128 * K_DIM;
    const __nv_bfloat16* xg = g_xh + (size_t)blockIdx.x * 128 * K_DIM;

    const uint32_t st0 = base, st1 = base + STAGE_BYTES, st2 = base + 2 * STAGE_BYTES;

    float acc[4][4][4];
#pragma unroll
    for (int mf = 0; mf < 4; ++mf)
#pragma unroll
        for (int nf = 0; nf < 4; ++nf)
#pragma unroll
            for (int q = 0; q < 4; ++q) acc[mf][nf][q] = 0.0f;

    // PDL: wait for round_kernel output before reading g_xh/g_zh
    cudaGridDependencySynchronize();

    // chunk order: 3 (hybrid), 0, 1, 2
    load_chunk(st0, zg, xg, 3, tid);
    load_chunk(st1, zg, xg, 0, tid);
    load_chunk(st2, zg, xg, 1, tid);

    asm volatile("cp.async.wait_group 2;\n" ::);
    __syncthreads();
    ffma_part(st0, m0, n0, lane, acc);            // k 240..255 on FMA pipe
    compute_chunk(st0, m0, n0, lane, acc, 3);     // k 192..239 on tensor pipe
    __syncthreads();                              // WAR before refilling st0
    load_chunk(st0, zg, xg, 2, tid);

    asm volatile("cp.async.wait_group 2;\n" ::);
    __syncthreads();
    compute_chunk(st1, m0, n0, lane, acc, 4);     // k 0..63

    asm volatile("cp.async.wait_group 1;\n" ::);
    __syncthreads();
    compute_chunk(st2, m0, n0, lane, acc, 4);     // k 64..127

    asm volatile("cp.async.wait_group 0;\n" ::);
    __syncthreads();
    compute_chunk(st0, m0, n0, lane, acc, 4);     // k 128..191

    // ---- epilogue: softmax over i (this warp's a-block), sum over j ----
    float sacc[2] = {0.f, 0.f};
#pragma unroll
    for (int mf = 0; mf < 4; ++mf) {
        const int bg = mf >> 1;
#pragma unroll
        for (int half = 0; half < 2; ++half) {
            float v[8];
#pragma unroll
            for (int nf = 0; nf < 4; ++nf) {
                v[nf * 2 + 0] = acc[mf][nf][half * 2 + 0];
                v[nf * 2 + 1] = acc[mf][nf][half * 2 + 1];
            }
            float mx = v[0];
#pragma unroll
            for (int t = 1; t < 8; ++t) mx = fmaxf(mx, v[t]);
            mx = fmaxf(mx, __shfl_xor_sync(0xffffffffu, mx, 1));
            mx = fmaxf(mx, __shfl_xor_sync(0xffffffffu, mx, 2));
            float den = 0.f, num = 0.f;
#pragma unroll
            for (int t = 0; t < 8; ++t) {
                float e = __expf(v[t] - mx);
                den += e;
                num += e * v[t];
            }
            den += __shfl_xor_sync(0xffffffffu, den, 1);
            num += __shfl_xor_sync(0xffffffffu, num, 1);
            den += __shfl_xor_sync(0xffffffffu, den, 2);
            num += __shfl_xor_sync(0xffffffffu, num, 2);
            sacc[bg] += num / den;
        }
    }
#pragma unroll
    for (int bg = 0; bg < 2; ++bg) {
        float s = sacc[bg];
        s += __shfl_xor_sync(0xffffffffu, s, 4);
        s += __shfl_xor_sync(0xffffffffu, s, 8);
        s += __shfl_xor_sync(0xffffffffu, s, 16);
        if (lane == 0) {
            int aIdx = blockIdx.x * 4 + w_n;
            int bIdx = blockIdx.y * 4 + w_m * 2 + bg;
            float val = s * (1.0f / 32.0f);
            g_S[aIdx * N_B + bIdx]  = val;
            g_St[bIdx * N_B + aIdx] = val;
        }
    }
}

// ---------------------------------------------------------------------------
// Phase 2: loss. 16 blocks x 256 threads; 512 lse tasks (4 per warp).
// ---------------------------------------------------------------------------
__global__ void loss_kernel(float* __restrict__ out) {
    __shared__ float bsum[8];
    const int warp = threadIdx.x >> 5;
    const int lane = threadIdx.x & 31;

    cudaGridDependencySynchronize();   // PDL: wait for sim_kernel

    float local = 0.f;
#pragma unroll 1
    for (int t = 0; t < 4; ++t) {
        const int id = blockIdx.x * 32 + warp * 4 + t;   // 0..511
        const int n  = id & (N_B - 1);
        const float* row = (id < N_B) ? (g_S + n * N_B) : (g_St + n * N_B);
        float4 r0 = ((const float4*)row)[lane];
        float4 r1 = ((const float4*)row)[lane + 32];
        float m = fmaxf(fmaxf(fmaxf(r0.x, r0.y), fmaxf(r0.z, r0.w)),
                        fmaxf(fmaxf(r1.x, r1.y), fmaxf(r1.z, r1.w)));
#pragma unroll
        for (int o = 16; o > 0; o >>= 1) m = fmaxf(m, __shfl_xor_sync(0xffffffffu, m, o));
        float s = __expf(r0.x - m) + __expf(r0.y - m) + __expf(r0.z - m) + __expf(r0.w - m)
                + __expf(r1.x - m) + __expf(r1.y - m) + __expf(r1.z - m) + __expf(r1.w - m);
#pragma unroll
        for (int o = 16; o > 0; o >>= 1) s += __shfl_xor_sync(0xffffffffu, s, o);
        if (lane == 0) local += m + logf(s) - g_S[n * N_B + n];
    }
    if (lane == 0) bsum[warp] = local;
    __syncthreads();

    if (threadIdx.x == 0) {
        float bs = 0.f;
#pragma unroll
        for (int w = 0; w < 8; ++w) bs += bsum[w];
        g_bpart[blockIdx.x] = bs;
        __threadfence();
        unsigned ticket = atomicAdd(&g_cnt, 1u);
        if (ticket == gridDim.x - 1) {
            __threadfence();
            float tot = 0.f;
#pragma unroll
            for (int b = 0; b < 16; ++b) tot += g_bpart[b];
            out[0] = tot * (1.0f / (float)N_B);
            g_cnt = 0;                        // reset for next graph replay
        }
    }
}

// ---------------------------------------------------------------------------
extern "C" void kernel_launch(void* const* d_in, const int* in_sizes, int n_in,
                              void* d_out, int out_size) {
    (void)in_sizes; (void)n_in; (void)out_size;
    const float* x = (const float*)d_in[0];
    const float* z = (const float*)d_in[1];
    float* out = (float*)d_out;

    static int configured = 0;
    if (!configured) {
        cudaFuncSetAttribute(sim_kernel, cudaFuncAttributeMaxDynamicSharedMemorySize, SM_ALLOC);
        configured = 1;
    }

    round_kernel<<<512, 256>>>(x, z);

    // sim with PDL dependency on round
    {
        cudaLaunchAttribute attr[1];
        attr[0].id = cudaLaunchAttributeProgrammaticStreamSerialization;
        attr[0].val.programmaticStreamSerializationAllowed = 1;
        cudaLaunchConfig_t cfg = {};
        cfg.gridDim  = dim3(64, 64);
        cfg.blockDim = dim3(256);
        cfg.dynamicSmemBytes = SM_ALLOC;
        cfg.stream = 0;
        cfg.attrs = attr;
        cfg.numAttrs = 1;
        cudaLaunchKernelEx(&cfg, sim_kernel);
    }

    // loss with PDL dependency on sim
    {
        cudaLaunchAttribute attr[1];
        attr[0].id = cudaLaunchAttributeProgrammaticStreamSerialization;
        attr[0].val.programmaticStreamSerializationAllowed = 1;
        cudaLaunchConfig_t cfg = {};
        cfg.gridDim  = dim3(16);
        cfg.blockDim = dim3(256);
        cfg.dynamicSmemBytes = 0;
        cfg.stream = 0;
        cfg.attrs = attr;
        cfg.numAttrs = 1;
        cudaLaunchKernelEx(&cfg, loss_kernel, out);
    }
}

// round 15
// speedup vs baseline: 1.1573x; 1.1573x over previous
#include <cuda_runtime.h>
#include <cuda_bf16.h>
#include <cstdint>
#include <math.h>

#define N_B   256
#define K_DIM 256
// mma roles: M = 128 z-rows (4 b's), N = 128 x-rows (4 a's) per CTA
#define KC 64                    // bf16 per chunk = 128 B rows
#define NCHUNK (K_DIM / KC)      // 4

// per stage: Z 128*128B = 16KB + X 128*128B = 16KB = 32KB; 3 stages
#define STAGE_BYTES 32768
#define SM_ALLOC (3 * STAGE_BYTES + 1024)

// device scratch (allocation-free rule)
__device__ __align__(1024) __nv_bfloat16 g_xh[(size_t)N_B * 32 * K_DIM];
__device__ __align__(1024) __nv_bfloat16 g_zh[(size_t)N_B * 32 * K_DIM];
__device__ __align__(256)  float g_S[N_B * N_B];
__device__ __align__(256)  float g_St[N_B * N_B];
__device__ float g_bpart[16];
__device__ unsigned g_cnt;

// ---------------------------------------------------------------------------
__device__ __forceinline__ uint32_t smem_u32(const void* p) {
    uint32_t a;
    asm("{ .reg .u64 t; cvta.to.shared.u64 t, %1; cvt.u32.u64 %0, t; }" : "=r"(a) : "l"(p));
    return a;
}
__device__ __forceinline__ void cp16(uint32_t dst, const void* src) {
    asm volatile("cp.async.cg.shared.global [%0], [%1], 16;\n" :: "r"(dst), "l"(src));
}
__device__ __forceinline__ void ldm_x4(uint32_t r[4], uint32_t addr) {
    asm volatile("ldmatrix.sync.aligned.m8n8.x4.shared.b16 {%0,%1,%2,%3}, [%4];"
                 : "=r"(r[0]), "=r"(r[1]), "=r"(r[2]), "=r"(r[3]) : "r"(addr));
}
__device__ __forceinline__ void mma_bf16(float c[4], const uint32_t a[4], const uint32_t b0,
                                         const uint32_t b1) {
    asm volatile(
        "mma.sync.aligned.m16n8k16.row.col.f32.bf16.bf16.f32 "
        "{%0,%1,%2,%3}, {%4,%5,%6,%7}, {%8,%9}, {%0,%1,%2,%3};\n"
        : "+f"(c[0]), "+f"(c[1]), "+f"(c[2]), "+f"(c[3])
        : "r"(a[0]), "r"(a[1]), "r"(a[2]), "r"(a[3]), "r"(b0), "r"(b1));
}
__device__ __forceinline__ uint32_t swz(uint32_t off) {
    return off ^ ((off >> 3) & 0x70);
}
__device__ __forceinline__ uint2 bf4(float4 v) {
    __nv_bfloat162 p0 = __floats2bfloat162_rn(v.x, v.y);
    __nv_bfloat162 p1 = __floats2bfloat162_rn(v.z, v.w);
    uint2 o;
    o.x = *(uint32_t*)&p0;
    o.y = *(uint32_t*)&p1;
    return o;
}

// ---------------------------------------------------------------------------
// Phase 0: fp32 -> bf16 (rn); 8 independent float4 per thread (MLP 8)
// ---------------------------------------------------------------------------
__global__ void round_kernel(const float* __restrict__ x, const float* __restrict__ z) {
    const int qtr = (N_B * 32 * K_DIM) / 16;         // 131072 float4 per quarter-tensor
    int i = blockIdx.x * blockDim.x + threadIdx.x;   // 0..131071
    float4 vx0 = ((const float4*)x)[i];
    float4 vx1 = ((const float4*)x)[i + qtr];
    float4 vx2 = ((const float4*)x)[i + 2 * qtr];
    float4 vx3 = ((const float4*)x)[i + 3 * qtr];
    float4 vz0 = ((const float4*)z)[i];
    float4 vz1 = ((const float4*)z)[i + qtr];
    float4 vz2 = ((const float4*)z)[i + 2 * qtr];
    float4 vz3 = ((const float4*)z)[i + 3 * qtr];
    *(uint2*)(g_xh + 4 * (size_t)i)             = bf4(vx0);
    *(uint2*)(g_xh + 4 * (size_t)(i + qtr))     = bf4(vx1);
    *(uint2*)(g_xh + 4 * (size_t)(i + 2 * qtr)) = bf4(vx2);
    *(uint2*)(g_xh + 4 * (size_t)(i + 3 * qtr)) = bf4(vx3);
    *(uint2*)(g_zh + 4 * (size_t)i)             = bf4(vz0);
    *(uint2*)(g_zh + 4 * (size_t)(i + qtr))     = bf4(vz1);
    *(uint2*)(g_zh + 4 * (size_t)(i + 2 * qtr)) = bf4(vz2);
    *(uint2*)(g_zh + 4 * (size_t)(i + 3 * qtr)) = bf4(vz3);
}

// ---------------------------------------------------------------------------
// Phase 1: bf16 mma.sync (rows = z, cols = x), 128x128 tile, 2 CTAs/SM
// (bit-identical to the measured 102.6us R12 kernel — at the HMMA issue floor)
// ---------------------------------------------------------------------------
__device__ __forceinline__ void load_chunk(uint32_t stg,
                                           const __nv_bfloat16* __restrict__ zg,
                                           const __nv_bfloat16* __restrict__ xg,
                                           int c, int tid) {
    const int kc = c * KC;
    const uint32_t zs = stg;
    const uint32_t xs = stg + 16384;
#pragma unroll
    for (int q = 0; q < 4; ++q) {            // Z: 128 rows x 8 segs
        int it = tid + 256 * q;
        int row = it >> 3, s = it & 7;
        cp16(zs + swz(row * 128 + s * 16), zg + (size_t)row * K_DIM + kc + s * 8);
    }
#pragma unroll
    for (int q = 0; q < 4; ++q) {            // X: 128 rows x 8 segs
        int it = tid + 256 * q;
        int row = it >> 3, s = it & 7;
        cp16(xs + swz(row * 128 + s * 16), xg + (size_t)row * K_DIM + kc + s * 8);
    }
    asm volatile("cp.async.commit_group;\n" ::);
}

__device__ __forceinline__ void compute_chunk(uint32_t stg, int m0, int n0, int lane,
                                              float acc[4][4][4]) {
    const uint32_t zs = stg;
    const uint32_t xs = stg + 16384;
    const int a_row16 = lane & 15;
    const int a_half  = lane >> 4;
    const int b_grp   = lane >> 3;
    const int b_row   = lane & 7;
#pragma unroll
    for (int ks = 0; ks < 4; ++ks) {
        const uint32_t kcol = ks * 32;
        uint32_t a[4][4];
#pragma unroll
        for (int mf = 0; mf < 4; ++mf) {     // A = z rows
            int row = m0 + mf * 16 + a_row16;
            ldm_x4(a[mf], zs + swz((uint32_t)row * 128 + kcol + a_half * 16));
        }
        uint32_t b[2][4];
#pragma unroll
        for (int pf = 0; pf < 2; ++pf) {     // B = x rows (n range 32)
            int row = n0 + pf * 16 + (b_grp >> 1) * 8 + b_row;
            ldm_x4(b[pf], xs + swz((uint32_t)row * 128 + kcol + (b_grp & 1) * 16));
        }
#pragma unroll
        for (int mf = 0; mf < 4; ++mf)
#pragma unroll
            for (int nf = 0; nf < 4; ++nf)
                mma_bf16(acc[mf][nf], a[mf], b[nf >> 1][(nf & 1) * 2],
                         b[nf >> 1][(nf & 1) * 2 + 1]);
    }
}

__global__ void __launch_bounds__(256, 2) sim_kernel() {
    extern __shared__ char sm_raw[];
    uint32_t base = (smem_u32(sm_raw) + 1023u) & ~1023u;

    const int tid  = threadIdx.x;
    const int lane = tid & 31;
    const int wid  = tid >> 5;
    const int w_m  = wid & 1;       // 2 warps over 128 z rows
    const int w_n  = wid >> 1;      // 4 warps over 128 x rows
    const int m0   = w_m * 64;
    const int n0   = w_n * 32;

    const __nv_bfloat16* zg = g_zh + (size_t)blockIdx.y * 128 * K_DIM;
    const __nv_bfloat16* xg = g_xh + (size_t)blockIdx.x * 128 * K_DIM;

    const uint32_t st0 = base, st1 = base + STAGE_BYTES, st2 = base + 2 * STAGE_BYTES;

    float acc[4][4][4];
#pragma unroll
    for (int mf = 0; mf < 4; ++mf)
#pragma unroll
        for (int nf = 0; nf < 4; ++nf)
#pragma unroll
            for (int q = 0; q < 4; ++q) acc[mf][nf][q] = 0.0f;

    // PDL: wait for round_kernel to complete before reading g_xh/g_zh
    cudaGridDependencySynchronize();

    load_chunk(st0, zg, xg, 0, tid);
    load_chunk(st1, zg, xg, 1, tid);
    load_chunk(st2, zg, xg, 2, tid);

    asm volatile("cp.async.wait_group 2;\n" ::);
    __syncthreads();
    compute_chunk(st0, m0, n0, lane, acc);
    __syncthreads();                          // WAR before refilling stage 0
    load_chunk(st0, zg, xg, 3, tid);

    asm volatile("cp.async.wait_group 2;\n" ::);
    __syncthreads();
    compute_chunk(st1, m0, n0, lane, acc);

    asm volatile("cp.async.wait_group 1;\n" ::);
    __syncthreads();
    compute_chunk(st2, m0, n0, lane, acc);

    asm volatile("cp.async.wait_group 0;\n" ::);
    __syncthreads();
    compute_chunk(st0, m0, n0, lane, acc);

    // ---- epilogue: softmax over i (this warp's a-block), sum over j ----
    float sacc[2] = {0.f, 0.f};
#pragma unroll
    for (int mf = 0; mf < 4; ++mf) {
        const int bg = mf >> 1;
#pragma unroll
        for (int half = 0; half < 2; ++half) {
            float v[8];
#pragma unroll
            for (int nf = 0; nf < 4; ++nf) {
                v[nf * 2 + 0] = acc[mf][nf][half * 2 + 0];
                v[nf * 2 + 1] = acc[mf][nf][half * 2 + 1];
            }
            float mx = v[0];
#pragma unroll
            for (int t = 1; t < 8; ++t) mx = fmaxf(mx, v[t]);
            mx = fmaxf(mx, __shfl_xor_sync(0xffffffffu, mx, 1));
            mx = fmaxf(mx, __shfl_xor_sync(0xffffffffu, mx, 2));
            float den = 0.f, num = 0.f;
#pragma unroll
            for (int t = 0; t < 8; ++t) {
                float e = __expf(v[t] - mx);
                den += e;
                num += e * v[t];
            }
            den += __shfl_xor_sync(0xffffffffu, den, 1);
            num += __shfl_xor_sync(0xffffffffu, num, 1);
            den += __shfl_xor_sync(0xffffffffu, den, 2);
            num += __shfl_xor_sync(0xffffffffu, num, 2);
            sacc[bg] += num / den;
        }
    }
#pragma unroll
    for (int bg = 0; bg < 2; ++bg) {
        float s = sacc[bg];
        s += __shfl_xor_sync(0xffffffffu, s, 4);
        s += __shfl_xor_sync(0xffffffffu, s, 8);
        s += __shfl_xor_sync(0xffffffffu, s, 16);
        if (lane == 0) {
            int aIdx = blockIdx.x * 4 + w_n;
            int bIdx = blockIdx.y * 4 + w_m * 2 + bg;
            float val = s * (1.0f / 32.0f);
            g_S[aIdx * N_B + bIdx]  = val;
            g_St[bIdx * N_B + aIdx] = val;
        }
    }
}

// ---------------------------------------------------------------------------
// Phase 2: loss. 16 blocks x 256 threads; 512 lse tasks (4 per warp).
// ---------------------------------------------------------------------------
__global__ void loss_kernel(float* __restrict__ out) {
    __shared__ float bsum[8];
    const int warp = threadIdx.x >> 5;
    const int lane = threadIdx.x & 31;

    // PDL: wait for sim_kernel to finish writing g_S/g_St
    cudaGridDependencySynchronize();

    float local = 0.f;
#pragma unroll 1
    for (int t = 0; t < 4; ++t) {
        const int id = blockIdx.x * 32 + warp * 4 + t;   // 0..511
        const int n  = id & (N_B - 1);
        const float* row = (id < N_B) ? (g_S + n * N_B) : (g_St + n * N_B);
        float4 r0 = ((const float4*)row)[lane];
        float4 r1 = ((const float4*)row)[lane + 32];
        float m = fmaxf(fmaxf(fmaxf(r0.x, r0.y), fmaxf(r0.z, r0.w)),
                        fmaxf(fmaxf(r1.x, r1.y), fmaxf(r1.z, r1.w)));
#pragma unroll
        for (int o = 16; o > 0; o >>= 1) m = fmaxf(m, __shfl_xor_sync(0xffffffffu, m, o));
        float s = __expf(r0.x - m) + __expf(r0.y - m) + __expf(r0.z - m) + __expf(r0.w - m)
                + __expf(r1.x - m) + __expf(r1.y - m) + __expf(r1.z - m) + __expf(r1.w - m);
#pragma unroll
        for (int o = 16; o > 0; o >>= 1) s += __shfl_xor_sync(0xffffffffu, s, o);
        if (lane == 0) local += m + logf(s) - g_S[n * N_B + n];
    }
    if (lane == 0) bsum[warp] = local;
    __syncthreads();

    if (threadIdx.x == 0) {
        float bs = 0.f;
#pragma unroll
        for (int w = 0; w < 8; ++w) bs += bsum[w];
        g_bpart[blockIdx.x] = bs;
        __threadfence();
        unsigned ticket = atomicAdd(&g_cnt, 1u);
        if (ticket == gridDim.x - 1) {
            __threadfence();
            float tot = 0.f;
#pragma unroll
            for (int b = 0; b < 16; ++b) tot += g_bpart[b];
            out[0] = tot * (1.0f / (float)N_B);
            g_cnt = 0;                        // reset for next graph replay
        }
    }
}

// ---------------------------------------------------------------------------
extern "C" void kernel_launch(void* const* d_in, const int* in_sizes, int n_in,
                              void* d_out, int out_size) {
    (void)in_sizes; (void)n_in; (void)out_size;
    const float* x = (const float*)d_in[0];
    const float* z = (const float*)d_in[1];
    float* out = (float*)d_out;

    static int configured = 0;
    if (!configured) {
        cudaFuncSetAttribute(sim_kernel, cudaFuncAttributeMaxDynamicSharedMemorySize, SM_ALLOC);
        configured = 1;
    }

    round_kernel<<<512, 256>>>(x, z);

    // sim with PDL dependency on round
    {
        cudaLaunchAttribute attr[1];
        attr[0].id = cudaLaunchAttributeProgrammaticStreamSerialization;
        attr[0].val.programmaticStreamSerializationAllowed = 1;
        cudaLaunchConfig_t cfg = {};
        cfg.gridDim  = dim3(64, 64);
        cfg.blockDim = dim3(256);
        cfg.dynamicSmemBytes = SM_ALLOC;
        cfg.stream = 0;
        cfg.attrs = attr;
        cfg.numAttrs = 1;
        cudaLaunchKernelEx(&cfg, sim_kernel);
    }

    // loss with PDL dependency on sim
    {
        cudaLaunchAttribute attr[1];
        attr[0].id = cudaLaunchAttributeProgrammaticStreamSerialization;
        attr[0].val.programmaticStreamSerializationAllowed = 1;
        cudaLaunchConfig_t cfg = {};
        cfg.gridDim  = dim3(16);
        cfg.blockDim = dim3(256);
        cfg.dynamicSmemBytes = 0;
        cfg.stream = 0;
        cfg.attrs = attr;
        cfg.numAttrs = 1;
        cudaLaunchKernelEx(&cfg, loss_kernel, out);
    }
}

// round 16
// speedup vs baseline: 1.7741x; 1.5330x over previous
#include <cuda_runtime.h>
#include <cuda_bf16.h>
#include <cstdint>
#include <math.h>

#define N_B   256
#define K_DIM 256
// mma roles: M = 128 z-rows (4 b's), N = 128 x-rows (4 a's) per CTA
#define KC 64                    // bf16 per chunk = 128 B rows
#define NCHUNK (K_DIM / KC)      // 4

// per stage: Z 128*128B = 16KB + X 128*128B = 16KB = 32KB; 3 stages
#define STAGE_BYTES 32768
#define SM_ALLOC (3 * STAGE_BYTES + 1024)

// device scratch (allocation-free rule)
__device__ __align__(1024) __nv_bfloat16 g_xh[(size_t)N_B * 32 * K_DIM];
__device__ __align__(1024) __nv_bfloat16 g_zh[(size_t)N_B * 32 * K_DIM];
__device__ __align__(256)  float g_S[N_B * N_B];
__device__ __align__(256)  float g_St[N_B * N_B];
__device__ float g_bpart[16];
__device__ unsigned g_cnt;

// ---------------------------------------------------------------------------
__device__ __forceinline__ uint32_t smem_u32(const void* p) {
    uint32_t a;
    asm("{ .reg .u64 t; cvta.to.shared.u64 t, %1; cvt.u32.u64 %0, t; }" : "=r"(a) : "l"(p));
    return a;
}
__device__ __forceinline__ void cp16(uint32_t dst, const void* src) {
    asm volatile("cp.async.cg.shared.global [%0], [%1], 16;\n" :: "r"(dst), "l"(src));
}
__device__ __forceinline__ void ldm_x4(uint32_t r[4], uint32_t addr) {
    asm volatile("ldmatrix.sync.aligned.m8n8.x4.shared.b16 {%0,%1,%2,%3}, [%4];"
                 : "=r"(r[0]), "=r"(r[1]), "=r"(r[2]), "=r"(r[3]) : "r"(addr));
}
__device__ __forceinline__ void mma_bf16(float c[4], const uint32_t a[4], const uint32_t b0,
                                         const uint32_t b1) {
    asm volatile(
        "mma.sync.aligned.m16n8k16.row.col.f32.bf16.bf16.f32 "
        "{%0,%1,%2,%3}, {%4,%5,%6,%7}, {%8,%9}, {%0,%1,%2,%3};\n"
        : "+f"(c[0]), "+f"(c[1]), "+f"(c[2]), "+f"(c[3])
        : "r"(a[0]), "r"(a[1]), "r"(a[2]), "r"(a[3]), "r"(b0), "r"(b1));
}
__device__ __forceinline__ uint32_t swz(uint32_t off) {
    return off ^ ((off >> 3) & 0x70);
}
__device__ __forceinline__ uint2 bf4(float4 v) {
    __nv_bfloat162 p0 = __floats2bfloat162_rn(v.x, v.y);
    __nv_bfloat162 p1 = __floats2bfloat162_rn(v.z, v.w);
    uint2 o;
    o.x = *(uint32_t*)&p0;
    o.y = *(uint32_t*)&p1;
    return o;
}

// ---------------------------------------------------------------------------
// Phase 0: fp32 -> bf16 (rn); 8 independent float4 per thread (MLP 8)
// ---------------------------------------------------------------------------
__global__ void round_kernel(const float* __restrict__ x, const float* __restrict__ z) {
    const int qtr = (N_B * 32 * K_DIM) / 16;         // 131072 float4 per quarter-tensor
    int i = blockIdx.x * blockDim.x + threadIdx.x;   // 0..131071
    float4 vx0 = ((const float4*)x)[i];
    float4 vx1 = ((const float4*)x)[i + qtr];
    float4 vx2 = ((const float4*)x)[i + 2 * qtr];
    float4 vx3 = ((const float4*)x)[i + 3 * qtr];
    float4 vz0 = ((const float4*)z)[i];
    float4 vz1 = ((const float4*)z)[i + qtr];
    float4 vz2 = ((const float4*)z)[i + 2 * qtr];
    float4 vz3 = ((const float4*)z)[i + 3 * qtr];
    *(uint2*)(g_xh + 4 * (size_t)i)             = bf4(vx0);
    *(uint2*)(g_xh + 4 * (size_t)(i + qtr))     = bf4(vx1);
    *(uint2*)(g_xh + 4 * (size_t)(i + 2 * qtr)) = bf4(vx2);
    *(uint2*)(g_xh + 4 * (size_t)(i + 3 * qtr)) = bf4(vx3);
    *(uint2*)(g_zh + 4 * (size_t)i)             = bf4(vz0);
    *(uint2*)(g_zh + 4 * (size_t)(i + qtr))     = bf4(vz1);
    *(uint2*)(g_zh + 4 * (size_t)(i + 2 * qtr)) = bf4(vz2);
    *(uint2*)(g_zh + 4 * (size_t)(i + 3 * qtr)) = bf4(vz3);
}

// ---------------------------------------------------------------------------
// Phase 1: bf16 mma.sync (rows = z, cols = x), 128x128 tile, 2 CTAs/SM
// (bit-identical to the measured 102.6us R12 kernel — at the HMMA issue floor)
// ---------------------------------------------------------------------------
__device__ __forceinline__ void load_chunk(uint32_t stg,
                                           const __nv_bfloat16* __restrict__ zg,
                                           const __nv_bfloat16* __restrict__ xg,
                                           int c, int tid) {
    const int kc = c * KC;
    const uint32_t zs = stg;
    const uint32_t xs = stg + 16384;
#pragma unroll
    for (int q = 0; q < 4; ++q) {            // Z: 128 rows x 8 segs
        int it = tid + 256 * q;
        int row = it >> 3, s = it & 7;
        cp16(zs + swz(row * 128 + s * 16), zg + (size_t)row * K_DIM + kc + s * 8);
    }
#pragma unroll
    for (int q = 0; q < 4; ++q) {            // X: 128 rows x 8 segs
        int it = tid + 256 * q;
        int row = it >> 3, s = it & 7;
        cp16(xs + swz(row * 128 + s * 16), xg + (size_t)row * K_DIM + kc + s * 8);
    }
    asm volatile("cp.async.commit_group;\n" ::);
}

__device__ __forceinline__ void compute_chunk(uint32_t stg, int m0, int n0, int lane,
                                              float acc[4][4][4]) {
    const uint32_t zs = stg;
    const uint32_t xs = stg + 16384;
    const int a_row16 = lane & 15;
    const int a_half  = lane >> 4;
    const int b_grp   = lane >> 3;
    const int b_row   = lane & 7;
#pragma unroll
    for (int ks = 0; ks < 4; ++ks) {
        const uint32_t kcol = ks * 32;
        uint32_t a[4][4];
#pragma unroll
        for (int mf = 0; mf < 4; ++mf) {     // A = z rows
            int row = m0 + mf * 16 + a_row16;
            ldm_x4(a[mf], zs + swz((uint32_t)row * 128 + kcol + a_half * 16));
        }
        uint32_t b[2][4];
#pragma unroll
        for (int pf = 0; pf < 2; ++pf) {     // B = x rows (n range 32)
            int row = n0 + pf * 16 + (b_grp >> 1) * 8 + b_row;
            ldm_x4(b[pf], xs + swz((uint32_t)row * 128 + kcol + (b_grp & 1) * 16));
        }
#pragma unroll
        for (int mf = 0; mf < 4; ++mf)
#pragma unroll
            for (int nf = 0; nf < 4; ++nf)
                mma_bf16(acc[mf][nf], a[mf], b[nf >> 1][(nf & 1) * 2],
                         b[nf >> 1][(nf & 1) * 2 + 1]);
    }
}

__global__ void __launch_bounds__(256, 2) sim_kernel() {
    extern __shared__ char sm_raw[];
    uint32_t base = (smem_u32(sm_raw) + 1023u) & ~1023u;

    const int tid  = threadIdx.x;
    const int lane = tid & 31;
    const int wid  = tid >> 5;
    const int w_m  = wid & 1;       // 2 warps over 128 z rows
    const int w_n  = wid >> 1;      // 4 warps over 128 x rows
    const int m0   = w_m * 64;
    const int n0   = w_n * 32;

    const __nv_bfloat16* zg = g_zh + (size_t)blockIdx.y * 128 * K_DIM;
    const __nv_bfloat16* xg = g_xh + (size_t)blockIdx.x * 128 * K_DIM;

    const uint32_t st0 = base, st1 = base + STAGE_BYTES, st2 = base + 2 * STAGE_BYTES;

    float acc[4][4][4];
#pragma unroll
    for (int mf = 0; mf < 4; ++mf)
#pragma unroll
        for (int nf = 0; nf < 4; ++nf)
#pragma unroll
            for (int q = 0; q < 4; ++q) acc[mf][nf][q] = 0.0f;

    // PDL: wait for round_kernel to complete before reading g_xh/g_zh
    cudaGridDependencySynchronize();

    load_chunk(st0, zg, xg, 0, tid);
    load_chunk(st1, zg, xg, 1, tid);
    load_chunk(st2, zg, xg, 2, tid);

    asm volatile("cp.async.wait_group 2;\n" ::);
    __syncthreads();
    compute_chunk(st0, m0, n0, lane, acc);
    __syncthreads();                          // WAR before refilling stage 0
    load_chunk(st0, zg, xg, 3, tid);

    asm volatile("cp.async.wait_group 2;\n" ::);
    __syncthreads();
    compute_chunk(st1, m0, n0, lane, acc);

    asm volatile("cp.async.wait_group 1;\n" ::);
    __syncthreads();
    compute_chunk(st2, m0, n0, lane, acc);

    asm volatile("cp.async.wait_group 0;\n" ::);
    __syncthreads();
    compute_chunk(st0, m0, n0, lane, acc);

    // ---- epilogue: softmax over i (this warp's a-block), sum over j ----
    float sacc[2] = {0.f, 0.f};
#pragma unroll
    for (int mf = 0; mf < 4; ++mf) {
        const int bg = mf >> 1;
#pragma unroll
        for (int half = 0; half < 2; ++half) {
            float v[8];
#pragma unroll
            for (int nf = 0; nf < 4; ++nf) {
                v[nf * 2 + 0] = acc[mf][nf][half * 2 + 0];
                v[nf * 2 + 1] = acc[mf][nf][half * 2 + 1];
            }
            float mx = v[0];
#pragma unroll
            for (int t = 1; t < 8; ++t) mx = fmaxf(mx, v[t]);
            mx = fmaxf(mx, __shfl_xor_sync(0xffffffffu, mx, 1));
            mx = fmaxf(mx, __shfl_xor_sync(0xffffffffu, mx, 2));
            float den = 0.f, num = 0.f;
#pragma unroll
            for (int t = 0; t < 8; ++t) {
                float e = __expf(v[t] - mx);
                den += e;
                num += e * v[t];
            }
            den += __shfl_xor_sync(0xffffffffu, den, 1);
            num += __shfl_xor_sync(0xffffffffu, num, 1);
            den += __shfl_xor_sync(0xffffffffu, den, 2);
            num += __shfl_xor_sync(0xffffffffu, num, 2);
            sacc[bg] += num / den;
        }
    }
#pragma unroll
    for (int bg = 0; bg < 2; ++bg) {
        float s = sacc[bg];
        s += __shfl_xor_sync(0xffffffffu, s, 4);
        s += __shfl_xor_sync(0xffffffffu, s, 8);
        s += __shfl_xor_sync(0xffffffffu, s, 16);
        if (lane == 0) {
            int aIdx = blockIdx.x * 4 + w_n;
            int bIdx = blockIdx.y * 4 + w_m * 2 + bg;
            float val = s * (1.0f / 32.0f);
            g_S[aIdx * N_B + bIdx]  = val;
            g_St[bIdx * N_B + aIdx] = val;
        }
    }
}

// ---------------------------------------------------------------------------
// Phase 2: loss. 16 blocks x 256 threads; 512 lse tasks (4 per warp).
// ---------------------------------------------------------------------------
__global__ void loss_kernel(float* __restrict__ out) {
    __shared__ float bsum[8];
    const int warp = threadIdx.x >> 5;
    const int lane = threadIdx.x & 31;

    // PDL: wait for sim_kernel to finish writing g_S/g_St
    cudaGridDependencySynchronize();

    float local = 0.f;
#pragma unroll 1
    for (int t = 0; t < 4; ++t) {
        const int id = blockIdx.x * 32 + warp * 4 + t;   // 0..511
        const int n  = id & (N_B - 1);
        const float* row = (id < N_B) ? (g_S + n * N_B) : (g_St + n * N_B);
        float4 r0 = ((const float4*)row)[lane];
        float4 r1 = ((const float4*)row)[lane + 32];
        float m = fmaxf(fmaxf(fmaxf(r0.x, r0.y), fmaxf(r0.z, r0.w)),
                        fmaxf(fmaxf(r1.x, r1.y), fmaxf(r1.z, r1.w)));
#pragma unroll
        for (int o = 16; o > 0; o >>= 1) m = fmaxf(m, __shfl_xor_sync(0xffffffffu, m, o));
        float s = __expf(r0.x - m) + __expf(r0.y - m) + __expf(r0.z - m) + __expf(r0.w - m)
                + __expf(r1.x - m) + __expf(r1.y - m) + __expf(r1.z - m) + __expf(r1.w - m);
#pragma unroll
        for (int o = 16; o > 0; o >>= 1) s += __shfl_xor_sync(0xffffffffu, s, o);
        if (lane == 0) local += m + logf(s) - g_S[n * N_B + n];
    }
    if (lane == 0) bsum[warp] = local;
    __syncthreads();

    if (threadIdx.x == 0) {
        float bs = 0.f;
#pragma unroll
        for (int w = 0; w < 8; ++w) bs += bsum[w];
        g_bpart[blockIdx.x] = bs;
        __threadfence();
        unsigned ticket = atomicAdd(&g_cnt, 1u);
        if (ticket == gridDim.x - 1) {
            __threadfence();
            float tot = 0.f;
#pragma unroll
            for (int b = 0; b < 16; ++b) tot += g_bpart[b];
            out[0] = tot * (1.0f / (float)N_B);
            g_cnt = 0;                        // reset for next graph replay
        }
    }
}

// ---------------------------------------------------------------------------
extern "C" void kernel_launch(void* const* d_in, const int* in_sizes, int n_in,
                              void* d_out, int out_size) {
    (void)in_sizes; (void)n_in; (void)out_size;
    const float* x = (const float*)d_in[0];
    const float* z = (const float*)d_in[1];
    float* out = (float*)d_out;

    static int configured = 0;
    if (!configured) {
        cudaFuncSetAttribute(sim_kernel, cudaFuncAttributeMaxDynamicSharedMemorySize, SM_ALLOC);
        configured = 1;
    }

    round_kernel<<<512, 256>>>(x, z);

    // sim with PDL dependency on round
    {
        cudaLaunchAttribute attr[1];
        attr[0].id = cudaLaunchAttributeProgrammaticStreamSerialization;
        attr[0].val.programmaticStreamSerializationAllowed = 1;
        cudaLaunchConfig_t cfg = {};
        cfg.gridDim  = dim3(64, 64);
        cfg.blockDim = dim3(256);
        cfg.dynamicSmemBytes = SM_ALLOC;
        cfg.stream = 0;
        cfg.attrs = attr;
        cfg.numAttrs = 1;
        cudaLaunchKernelEx(&cfg, sim_kernel);
    }

    // loss with PDL dependency on sim
    {
        cudaLaunchAttribute attr[1];
        attr[0].id = cudaLaunchAttributeProgrammaticStreamSerialization;
        attr[0].val.programmaticStreamSerializationAllowed = 1;
        cudaLaunchConfig_t cfg = {};
        cfg.gridDim  = dim3(16);
        cfg.blockDim = dim3(256);
        cfg.dynamicSmemBytes = 0;
        cfg.stream = 0;
        cfg.attrs = attr;
        cfg.numAttrs = 1;
        cudaLaunchKernelEx(&cfg, loss_kernel, out);
    }
}